// round 3
// baseline (speedup 1.0000x reference)
#include <cuda_runtime.h>
#include <math.h>

// Problem constants
namespace {
constexpr int Gd = 4, Td = 4096, Dd = 2048, Ed = 64, Cd = 128;
constexpr int GT = Gd * Td;                       // 16384 tokens total
constexpr long long GTEC = (long long)GT * Ed * Cd; // 134217728
constexpr int MBLOCKS = GT / 128;                 // 128 GEMM blocks
constexpr int ZBLOCKS = 896;                      // zero-fill blocks
}

// Scratch (fully overwritten every launch -> deterministic)
__device__ float g_gate1[GT];
__device__ float g_gate2[GT];
__device__ int   g_idx[GT];                 // idx1 | idx2<<8
__device__ float g_sumP_part[MBLOCKS][Ed];  // per-block sum of probs per expert
__device__ float g_z_part[MBLOCKS];         // per-block z-loss partial
__device__ int   g_cnt[Gd * Ed];            // tokens per (group, expert) in top-2

// ---------------------------------------------------------------------------
// Kernel 1 (fused): blocks [0,MBLOCKS) do GEMM+softmax+top2+loss partials,
// blocks [MBLOCKS, ...) zero-fill the entire output concurrently.
// ---------------------------------------------------------------------------
__global__ void __launch_bounds__(256) k_main(const float* __restrict__ X,
                                              const float* __restrict__ W,
                                              const float* __restrict__ bias_v,
                                              float* __restrict__ out,
                                              long long out_elems) {
    if (blockIdx.x >= MBLOCKS) {
        // ------------------ zero-fill role ------------------
        long long n4 = out_elems >> 2;
        float4 z4 = make_float4(0.f, 0.f, 0.f, 0.f);
        float4* o4 = (float4*)out;
        long long tid = (long long)(blockIdx.x - MBLOCKS) * blockDim.x + threadIdx.x;
        long long stride = (long long)(gridDim.x - MBLOCKS) * blockDim.x;
        for (long long i = tid; i < n4; i += stride) o4[i] = z4;
        if (blockIdx.x == MBLOCKS && threadIdx.x == 0) {
            for (long long i = n4 << 2; i < out_elems; i++) out[i] = 0.f;
        }
        return;
    }

    // ------------------ GEMM role: 128 rows x 64 cols, K=2048 ------------------
    __shared__ float As[16][128];      // [k][m]
    __shared__ float Bs[16][64];       // [k][e]
    __shared__ float tileS[128][65];   // logits -> probs
    __shared__ float rowz[128];

    const int tid = threadIdx.x;
    const int m0 = blockIdx.x * 128;
    const int tx = tid & 15;   // 16 in N dir -> 4 cols each
    const int ty = tid >> 4;   // 16 in M dir -> 8 rows each (4 row-pairs)

    // accumulators as packed f32x2: acc2[row_pair][col]
    unsigned long long acc2[4][4];
#pragma unroll
    for (int i = 0; i < 4; i++)
#pragma unroll
        for (int j = 0; j < 4; j++) acc2[i][j] = 0ull;

    // prefetch registers
    float4 xa0, xa1, wb;
    const int idA0 = tid;          // 512 float4s for the X tile
    const int idA1 = tid + 256;
    const int rA0 = idA0 >> 2, qA0 = idA0 & 3;
    const int rA1 = idA1 >> 2, qA1 = idA1 & 3;
    const int kkW = tid >> 4, e4W = tid & 15;

    // load tile 0
    xa0 = *(const float4*)&X[(long long)(m0 + rA0) * Dd + 0 + qA0 * 4];
    xa1 = *(const float4*)&X[(long long)(m0 + rA1) * Dd + 0 + qA1 * 4];
    wb  = *(const float4*)&W[(long long)(0 + kkW) * Ed + e4W * 4];
    As[qA0 * 4 + 0][rA0] = xa0.x; As[qA0 * 4 + 1][rA0] = xa0.y;
    As[qA0 * 4 + 2][rA0] = xa0.z; As[qA0 * 4 + 3][rA0] = xa0.w;
    As[qA1 * 4 + 0][rA1] = xa1.x; As[qA1 * 4 + 1][rA1] = xa1.y;
    As[qA1 * 4 + 2][rA1] = xa1.z; As[qA1 * 4 + 3][rA1] = xa1.w;
    *(float4*)&Bs[kkW][e4W * 4] = wb;
    __syncthreads();

    constexpr int NTILES = Dd / 16;   // 128
    for (int t = 0; t < NTILES; t++) {
        if (t + 1 < NTILES) {
            int k0 = (t + 1) * 16;
            xa0 = *(const float4*)&X[(long long)(m0 + rA0) * Dd + k0 + qA0 * 4];
            xa1 = *(const float4*)&X[(long long)(m0 + rA1) * Dd + k0 + qA1 * 4];
            wb  = *(const float4*)&W[(long long)(k0 + kkW) * Ed + e4W * 4];
        }
#pragma unroll
        for (int kk = 0; kk < 16; kk++) {
            ulonglong2 aA = *(const ulonglong2*)&As[kk][ty * 8];
            ulonglong2 aB = *(const ulonglong2*)&As[kk][ty * 8 + 4];
            unsigned long long ap[4] = {aA.x, aA.y, aB.x, aB.y};
            float4 bv = *(const float4*)&Bs[kk][tx * 4];
            unsigned long long bd[4];
            asm("mov.b64 %0, {%1,%1};" : "=l"(bd[0]) : "f"(bv.x));
            asm("mov.b64 %0, {%1,%1};" : "=l"(bd[1]) : "f"(bv.y));
            asm("mov.b64 %0, {%1,%1};" : "=l"(bd[2]) : "f"(bv.z));
            asm("mov.b64 %0, {%1,%1};" : "=l"(bd[3]) : "f"(bv.w));
#pragma unroll
            for (int i = 0; i < 4; i++)
#pragma unroll
                for (int j = 0; j < 4; j++)
                    asm("fma.rn.f32x2 %0, %1, %2, %0;"
                        : "+l"(acc2[i][j]) : "l"(ap[i]), "l"(bd[j]));
        }
        __syncthreads();
        if (t + 1 < NTILES) {
            As[qA0 * 4 + 0][rA0] = xa0.x; As[qA0 * 4 + 1][rA0] = xa0.y;
            As[qA0 * 4 + 2][rA0] = xa0.z; As[qA0 * 4 + 3][rA0] = xa0.w;
            As[qA1 * 4 + 0][rA1] = xa1.x; As[qA1 * 4 + 1][rA1] = xa1.y;
            As[qA1 * 4 + 2][rA1] = xa1.z; As[qA1 * 4 + 3][rA1] = xa1.w;
            *(float4*)&Bs[kkW][e4W * 4] = wb;
            __syncthreads();
        }
    }

    // unpack accumulators (+bias) into tileS as logits
    float bcol[4];
    *(float4*)bcol = *(const float4*)&bias_v[tx * 4];
#pragma unroll
    for (int i = 0; i < 4; i++) {
#pragma unroll
        for (int j = 0; j < 4; j++) {
            float lo, hi;
            asm("mov.b64 {%0,%1}, %2;" : "=f"(lo), "=f"(hi) : "l"(acc2[i][j]));
            tileS[ty * 8 + 2 * i + 0][tx * 4 + j] = lo + bcol[j];
            tileS[ty * 8 + 2 * i + 1][tx * 4 + j] = hi + bcol[j];
        }
    }
    __syncthreads();

    // per-row softmax / top-2 / z partial (each of 128 threads owns one row)
    if (tid < 128) {
        const int r = tid;
        const int row = m0 + r;
        float mx = -3.0e38f;
#pragma unroll 8
        for (int e = 0; e < Ed; e++) mx = fmaxf(mx, tileS[r][e]);
        float sum = 0.f;
        float l1 = -3.0e38f, l2 = -3.0e38f;
        int i1 = 0, i2 = 0;
        for (int e = 0; e < Ed; e++) {
            float L = tileS[r][e];
            sum += expf(L - mx);
            if (L > l1) { l2 = l1; i2 = i1; l1 = L; i1 = e; }
            else if (L > l2) { l2 = L; i2 = e; }
        }
        float lse = mx + logf(sum);
        float zr = 0.f;
        for (int e = 0; e < Ed; e++) {
            float d = tileS[r][e] - lse;
            zr += d * d;
        }
        rowz[r] = zr;
        g_gate1[row] = expf(l1 - mx) / sum;
        g_gate2[row] = expf(l2 - mx) / sum;
        g_idx[row] = i1 | (i2 << 8);
        // overwrite logits with probs (each thread only touches its own row)
        for (int e = 0; e < Ed; e++) tileS[r][e] = expf(tileS[r][e] - mx) / sum;
    }
    __syncthreads();

    // column sums of probs -> per-block partials for aux loss
    if (tid < 64) {
        float s = 0.f;
#pragma unroll 8
        for (int r = 0; r < 128; r++) s += tileS[r][tid];
        g_sumP_part[blockIdx.x][tid] = s;
    }
    // z partial reduce
    if (tid < 32) {
        float s = rowz[tid] + rowz[tid + 32] + rowz[tid + 64] + rowz[tid + 96];
#pragma unroll
        for (int o = 16; o; o >>= 1) s += __shfl_xor_sync(0xffffffffu, s, o);
        if (tid == 0) g_z_part[blockIdx.x] = s;
    }
}

// ---------------------------------------------------------------------------
// Kernel 2: per-group BPR sort + capacity assignment + sparse scatter.
// One block per group, 512 threads.
// ---------------------------------------------------------------------------
__global__ void __launch_bounds__(512) k_route(float* __restrict__ out) {
    __shared__ unsigned long long keys[4096];  // 32KB (later reused as hist)
    __shared__ unsigned short tok[4096];       // 8KB

    const int tid = threadIdx.x;
    const int g = blockIdx.x;
    const int lane = tid & 31;
    const int warp = tid >> 5;
    const unsigned lt = (1u << lane) - 1u;

    // build sort keys: descending gate1, ties -> ascending token index (stable)
    for (int i = tid; i < Td; i += 512) {
        unsigned u = __float_as_uint(g_gate1[g * Td + i]);
        unsigned o = (u >> 31) ? ~u : (u | 0x80000000u);   // ascending-order bits
        keys[i] = (((unsigned long long)(~o)) << 32) | (unsigned)i;
    }
    __syncthreads();

    // bitonic sort ascending (4096 elements)
    for (unsigned k = 2; k <= 4096; k <<= 1) {
        for (unsigned j = k >> 1; j > 0; j >>= 1) {
            for (unsigned i = tid; i < 4096; i += 512) {
                unsigned ixj = i ^ j;
                if (ixj > i) {
                    unsigned long long a = keys[i], b = keys[ixj];
                    bool up = ((i & k) == 0);
                    if ((a > b) == up) { keys[i] = b; keys[ixj] = a; }
                }
            }
            __syncthreads();
        }
    }

    // extract permutation, then reuse keys region as histogram
    for (int i = tid; i < Td; i += 512) tok[i] = (unsigned short)(keys[i] & 0xffffu);
    __syncthreads();

    unsigned short* hist = (unsigned short*)keys;  // [128 chunks][64 experts]
    unsigned* h32 = (unsigned*)keys;

    int tot1 = 0;  // per-expert top-1 totals kept in registers of threads tid<64

    for (int s = 0; s < 2; s++) {
        // zero histogram (8192 u16 = 4096 u32)
        for (int i = tid; i < 4096; i += 512) h32[i] = 0u;
        __syncthreads();

        int myE[8], myLr[8], myT[8];
#pragma unroll
        for (int jj = 0; jj < 8; jj++) {
            int c = warp * 8 + jj;          // chunk of 32 sorted positions
            int p = c * 32 + lane;
            int t = tok[p];
            int packed = g_idx[g * Td + t];
            int e = (s == 0) ? (packed & 0xff) : ((packed >> 8) & 0xff);
            unsigned m = __match_any_sync(0xffffffffu, e);
            int lr = __popc(m & lt);
            if ((m & lt) == 0) hist[c * 64 + e] = (unsigned short)__popc(m);
            myE[jj] = e; myLr[jj] = lr; myT[jj] = t;
        }
        __syncthreads();

        // exclusive scan over chunks per expert
        if (tid < 64) {
            int run = (s == 0) ? 0 : tot1;
            for (int c = 0; c < 128; c++) {
                int v = hist[c * 64 + tid];
                hist[c * 64 + tid] = (unsigned short)run;
                run += v;
            }
            if (s == 0) tot1 = run;
            else g_cnt[g * 64 + tid] = run;   // total top1+top2 count for aux loss
        }
        __syncthreads();

        // scatter nonzeros
        const float* gsrc = (s == 0) ? g_gate1 : g_gate2;
#pragma unroll
        for (int jj = 0; jj < 8; jj++) {
            int c = warp * 8 + jj;
            int pr = (int)hist[c * 64 + myE[jj]] + myLr[jj];
            if (pr < Cd) {
                long long idx = (((long long)(g * Td + myT[jj]) * Ed + myE[jj]) * Cd + pr);
                float gate = gsrc[g * Td + myT[jj]];
                out[idx] = 1.0f;          // dispatch
                out[GTEC + idx] = gate;   // combine
            }
        }
        __syncthreads();
    }
}

// ---------------------------------------------------------------------------
// Kernel 3: finalize aux_loss and z_loss scalars.
// ---------------------------------------------------------------------------
__global__ void __launch_bounds__(64) k_final(float* __restrict__ out) {
    __shared__ float red[4];
    int tid = threadIdx.x;  // 64 threads
    float term = 0.f;
    for (int g = 0; g < Gd; g++) {
        float sp = 0.f;
        for (int bb = 0; bb < 32; bb++) sp += g_sumP_part[g * 32 + bb][tid];
        term += (float)g_cnt[g * 64 + tid] * sp;
    }
    float z = g_z_part[tid] + g_z_part[tid + 64];
#pragma unroll
    for (int o = 16; o; o >>= 1) {
        term += __shfl_xor_sync(0xffffffffu, term, o);
        z += __shfl_xor_sync(0xffffffffu, z, o);
    }
    if ((tid & 31) == 0) { red[tid >> 5] = term; red[2 + (tid >> 5)] = z; }
    __syncthreads();
    if (tid == 0) {
        float T2 = red[0] + red[1];
        float Z2 = red[2] + red[3];
        // aux = E/(G*T^2) * sum_{g,e} cnt*sumP
        out[2 * GTEC]     = T2 * (64.0f / (4.0f * 4096.0f * 4096.0f));
        // z = mean over g,t,e of log_softmax^2
        out[2 * GTEC + 1] = Z2 * (1.0f / (4.0f * 4096.0f * 64.0f));
    }
}

// ---------------------------------------------------------------------------
extern "C" void kernel_launch(void* const* d_in, const int* in_sizes, int n_in,
                              void* d_out, int out_size) {
    const float* X = (const float*)d_in[0];
    const float* W = (const float*)d_in[1];
    const float* b = (const float*)d_in[2];
    float* out = (float*)d_out;

    k_main<<<MBLOCKS + ZBLOCKS, 256>>>(X, W, b, out, (long long)out_size);
    k_route<<<Gd, 512>>>(out);
    k_final<<<1, 64>>>(out);
}

// round 6
// speedup vs baseline: 1.0790x; 1.0790x over previous
#include <cuda_runtime.h>
#include <math.h>

// Problem constants
namespace {
constexpr int Gd = 4, Td = 4096, Dd = 2048, Ed = 64, Cd = 128;
constexpr int GT = Gd * Td;                         // 16384 tokens
constexpr long long GTEC = (long long)GT * Ed * Cd; // 134217728
constexpr int NB_G = 256;                           // GEMM blocks (64 rows each)
constexpr int NB_Z = 640;                           // zero-only blocks
constexpr int NBTOT = NB_G + NB_Z;                  // 896
constexpr long long N4 = (2 * GTEC) / 4;            // 67108864 float4s to zero
constexpr long long N_A = (N4 / 4) * 3;             // 50331648 (zero-only blocks)
constexpr long long PER_G = (N4 - N_A) / NB_G;      // 65536 float4 per GEMM block
}

// Scratch (fully overwritten every launch -> deterministic)
__device__ float g_gate1[GT];
__device__ float g_gate2[GT];
__device__ int   g_idx[GT];                // idx1 | idx2<<8
__device__ float g_sumP_part[NB_G][Ed];    // per-block sum of probs per expert
__device__ float g_z_part[NB_G];           // per-block z-loss partial
__device__ int   g_cnt[Gd * Ed];           // tokens per (group, expert) in top-2

// ---------------------------------------------------------------------------
// Kernel 1 (fused): blocks [0,NB_G) do 64-row GEMM+softmax+top2+loss partials
// then zero-fill their slice; blocks [NB_G,NBTOT) zero-fill region A.
// ---------------------------------------------------------------------------
__global__ void __launch_bounds__(256, 4) k_main(const float* __restrict__ X,
                                                  const float* __restrict__ W,
                                                  const float* __restrict__ bias_v,
                                                  float* __restrict__ out) {
    const int tid = threadIdx.x;
    const int bid = blockIdx.x;
    const float4 z4 = make_float4(0.f, 0.f, 0.f, 0.f);
    float4* o4 = (float4*)out;

    if (bid >= NB_G) {
        // ------------------ zero-fill role: region A ------------------
        long long i = (long long)(bid - NB_G) * 256 + tid;
        const long long stride = (long long)NB_Z * 256;
        for (; i < N_A; i += stride) __stcs(o4 + i, z4);
        return;
    }

    // ------------------ GEMM role: 64 rows x 64 cols, K=2048 ------------------
    __shared__ float smem_raw[64 * 65];     // 16.6KB, As/Bs union tileS
    __shared__ float rowz[64];
    float (*As)[64] = (float(*)[64])smem_raw;          // [16][64]
    float (*Bs)[64] = (float(*)[64])(smem_raw + 1024); // [16][64]
    float (*S)[65]  = (float(*)[65])smem_raw;          // [64][65] (after loop)

    const int m0 = bid * 64;
    const int tx = tid & 15;   // 16 in N dir -> 4 cols each
    const int ty = tid >> 4;   // 16 in M dir -> 4 rows each (2 row-pairs)

    unsigned long long acc2[2][4];
#pragma unroll
    for (int i = 0; i < 2; i++)
#pragma unroll
        for (int j = 0; j < 4; j++) acc2[i][j] = 0ull;

    const int rA = tid >> 2, qA = tid & 3;          // X tile: 256 float4s
    const int kkW = tid >> 4, e4W = tid & 15;       // W tile: 256 float4s
    const float* Xp = X + (long long)(m0 + rA) * Dd + qA * 4;
    const float* Wp = W + (long long)kkW * Ed + e4W * 4;

    float4 xa = *(const float4*)Xp;
    float4 wb = *(const float4*)Wp;
    As[qA * 4 + 0][rA] = xa.x; As[qA * 4 + 1][rA] = xa.y;
    As[qA * 4 + 2][rA] = xa.z; As[qA * 4 + 3][rA] = xa.w;
    *(float4*)&Bs[kkW][e4W * 4] = wb;
    __syncthreads();

    constexpr int NTILES = Dd / 16;   // 128
    for (int t = 0; t < NTILES; t++) {
        if (t + 1 < NTILES) {
            xa = *(const float4*)(Xp + (t + 1) * 16);
            wb = *(const float4*)(Wp + (long long)(t + 1) * 16 * Ed);
        }
#pragma unroll
        for (int kk = 0; kk < 16; kk++) {
            ulonglong2 aA = *(const ulonglong2*)&As[kk][ty * 4];
            unsigned long long ap[2] = {aA.x, aA.y};
            float4 bv = *(const float4*)&Bs[kk][tx * 4];
            unsigned long long bd[4];
            asm("mov.b64 %0, {%1,%1};" : "=l"(bd[0]) : "f"(bv.x));
            asm("mov.b64 %0, {%1,%1};" : "=l"(bd[1]) : "f"(bv.y));
            asm("mov.b64 %0, {%1,%1};" : "=l"(bd[2]) : "f"(bv.z));
            asm("mov.b64 %0, {%1,%1};" : "=l"(bd[3]) : "f"(bv.w));
#pragma unroll
            for (int i = 0; i < 2; i++)
#pragma unroll
                for (int j = 0; j < 4; j++)
                    asm("fma.rn.f32x2 %0, %1, %2, %0;"
                        : "+l"(acc2[i][j]) : "l"(ap[i]), "l"(bd[j]));
        }
        __syncthreads();
        if (t + 1 < NTILES) {
            As[qA * 4 + 0][rA] = xa.x; As[qA * 4 + 1][rA] = xa.y;
            As[qA * 4 + 2][rA] = xa.z; As[qA * 4 + 3][rA] = xa.w;
            *(float4*)&Bs[kkW][e4W * 4] = wb;
            __syncthreads();
        }
    }

    // unpack accumulators (+bias) into S as logits (As/Bs dead now)
    float bcol[4];
    *(float4*)bcol = *(const float4*)&bias_v[tx * 4];
#pragma unroll
    for (int i = 0; i < 2; i++) {
#pragma unroll
        for (int j = 0; j < 4; j++) {
            float lo, hi;
            asm("mov.b64 {%0,%1}, %2;" : "=f"(lo), "=f"(hi) : "l"(acc2[i][j]));
            S[ty * 4 + 2 * i + 0][tx * 4 + j] = lo + bcol[j];
            S[ty * 4 + 2 * i + 1][tx * 4 + j] = hi + bcol[j];
        }
    }
    __syncthreads();

    // per-row softmax / top-2 / z partial (64 rows, one thread per row)
    if (tid < 64) {
        const int r = tid;
        const int row = m0 + r;
        float mx = -3.0e38f;
#pragma unroll 8
        for (int e = 0; e < Ed; e++) mx = fmaxf(mx, S[r][e]);
        float sum = 0.f;
        float l1 = -3.0e38f, l2 = -3.0e38f;
        int i1 = 0, i2 = 0;
        for (int e = 0; e < Ed; e++) {
            float L = S[r][e];
            sum += expf(L - mx);
            if (L > l1) { l2 = l1; i2 = i1; l1 = L; i1 = e; }
            else if (L > l2) { l2 = L; i2 = e; }
        }
        float lse = mx + logf(sum);
        float zr = 0.f;
        for (int e = 0; e < Ed; e++) {
            float d = S[r][e] - lse;
            zr += d * d;
        }
        rowz[r] = zr;
        g_gate1[row] = expf(l1 - mx) / sum;
        g_gate2[row] = expf(l2 - mx) / sum;
        g_idx[row] = i1 | (i2 << 8);
        for (int e = 0; e < Ed; e++) S[r][e] = expf(S[r][e] - mx) / sum;
    }
    __syncthreads();

    // column sums of probs -> per-block partials for aux loss
    if (tid < 64) {
        float s = 0.f;
#pragma unroll 8
        for (int r = 0; r < 64; r++) s += S[r][tid];
        g_sumP_part[bid][tid] = s;
    }
    if (tid < 32) {
        float s = rowz[tid] + rowz[tid + 32];
#pragma unroll
        for (int o = 16; o; o >>= 1) s += __shfl_xor_sync(0xffffffffu, s, o);
        if (tid == 0) g_z_part[bid] = s;
    }

    // ------------------ zero-fill role: region B slice ------------------
    {
        long long s = N_A + (long long)bid * PER_G + tid;
#pragma unroll 4
        for (int i = 0; i < (int)(PER_G / 256); i++)
            __stcs(o4 + s + (long long)i * 256, z4);
    }
}

// ---------------------------------------------------------------------------
// Kernel 2: per-group BPR sort + capacity assignment + sparse scatter.
// One block per group, 1024 threads.
// ---------------------------------------------------------------------------
__global__ void __launch_bounds__(1024) k_route(float* __restrict__ out) {
    __shared__ unsigned long long keys[4096];  // 32KB (later reused as hist)
    __shared__ unsigned short tok[4096];       // 8KB

    const int tid = threadIdx.x;
    const int g = blockIdx.x;
    const int lane = tid & 31;
    const int warp = tid >> 5;                 // 0..31
    const unsigned lt = (1u << lane) - 1u;

    // keys: descending gate1, ties -> ascending token index (stable)
    for (int i = tid; i < Td; i += 1024) {
        unsigned u = __float_as_uint(g_gate1[g * Td + i]);
        unsigned o = (u >> 31) ? ~u : (u | 0x80000000u);
        keys[i] = (((unsigned long long)(~o)) << 32) | (unsigned)i;
    }
    __syncthreads();

    // bitonic sort ascending (4096 elements)
    for (unsigned k = 2; k <= 4096; k <<= 1) {
        for (unsigned j = k >> 1; j > 0; j >>= 1) {
            for (unsigned i = tid; i < 4096; i += 1024) {
                unsigned ixj = i ^ j;
                if (ixj > i) {
                    unsigned long long a = keys[i], b = keys[ixj];
                    bool up = ((i & k) == 0);
                    if ((a > b) == up) { keys[i] = b; keys[ixj] = a; }
                }
            }
            __syncthreads();
        }
    }

    for (int i = tid; i < Td; i += 1024) tok[i] = (unsigned short)(keys[i] & 0xffffu);
    __syncthreads();

    unsigned short* hist = (unsigned short*)keys;  // [128 chunks][64 experts]
    unsigned* h32 = (unsigned*)keys;

    int tot1 = 0;  // per-expert top-1 totals kept in registers of threads tid<64

    for (int s = 0; s < 2; s++) {
        for (int i = tid; i < 4096; i += 1024) h32[i] = 0u;
        __syncthreads();

        int myE[4], myLr[4], myT[4];
#pragma unroll
        for (int jj = 0; jj < 4; jj++) {
            int c = warp * 4 + jj;          // chunk of 32 sorted positions
            int p = c * 32 + lane;
            int t = tok[p];
            int packed = g_idx[g * Td + t];
            int e = (s == 0) ? (packed & 0xff) : ((packed >> 8) & 0xff);
            unsigned m = __match_any_sync(0xffffffffu, e);
            int lr = __popc(m & lt);
            if ((m & lt) == 0) hist[c * 64 + e] = (unsigned short)__popc(m);
            myE[jj] = e; myLr[jj] = lr; myT[jj] = t;
        }
        __syncthreads();

        // exclusive scan over chunks per expert
        if (tid < 64) {
            int run = (s == 0) ? 0 : tot1;
            for (int c = 0; c < 128; c++) {
                int v = hist[c * 64 + tid];
                hist[c * 64 + tid] = (unsigned short)run;
                run += v;
            }
            if (s == 0) tot1 = run;
            else g_cnt[g * 64 + tid] = run;
        }
        __syncthreads();

        const float* gsrc = (s == 0) ? g_gate1 : g_gate2;
#pragma unroll
        for (int jj = 0; jj < 4; jj++) {
            int c = warp * 4 + jj;
            int pr = (int)hist[c * 64 + myE[jj]] + myLr[jj];
            if (pr < Cd) {
                long long idx = (((long long)(g * Td + myT[jj]) * Ed + myE[jj]) * Cd + pr);
                float gate = gsrc[g * Td + myT[jj]];
                out[idx] = 1.0f;          // dispatch
                out[GTEC + idx] = gate;   // combine
            }
        }
        __syncthreads();
    }
}

// ---------------------------------------------------------------------------
// Kernel 3: finalize aux_loss and z_loss scalars.
// ---------------------------------------------------------------------------
__global__ void __launch_bounds__(64) k_final(float* __restrict__ out) {
    __shared__ float red[4];
    int tid = threadIdx.x;  // 64 threads
    float term = 0.f;
    for (int g = 0; g < Gd; g++) {
        float sp = 0.f;
        for (int bb = 0; bb < 64; bb++) sp += g_sumP_part[g * 64 + bb][tid];
        term += (float)g_cnt[g * 64 + tid] * sp;
    }
    float z = g_z_part[tid] + g_z_part[tid + 64] + g_z_part[tid + 128] + g_z_part[tid + 192];
#pragma unroll
    for (int o = 16; o; o >>= 1) {
        term += __shfl_xor_sync(0xffffffffu, term, o);
        z += __shfl_xor_sync(0xffffffffu, z, o);
    }
    if ((tid & 31) == 0) { red[tid >> 5] = term; red[2 + (tid >> 5)] = z; }
    __syncthreads();
    if (tid == 0) {
        float T2 = red[0] + red[1];
        float Z2 = red[2] + red[3];
        out[2 * GTEC]     = T2 * (64.0f / (4.0f * 4096.0f * 4096.0f));
        out[2 * GTEC + 1] = Z2 * (1.0f / (4.0f * 4096.0f * 64.0f));
    }
}

// ---------------------------------------------------------------------------
extern "C" void kernel_launch(void* const* d_in, const int* in_sizes, int n_in,
                              void* d_out, int out_size) {
    const float* X = (const float*)d_in[0];
    const float* W = (const float*)d_in[1];
    const float* b = (const float*)d_in[2];
    float* out = (float*)d_out;

    k_main<<<NBTOT, 256>>>(X, W, b, out);
    k_route<<<Gd, 1024>>>(out);
    k_final<<<1, 64>>>(out);
}